// round 15
// baseline (speedup 1.0000x reference)
#include <cuda_runtime.h>

#define SEQ    262144
#define HID    20
#define INP    9
#define CH     304
#define WARM   32
#define GROUP  16
#define R1     32               // h1 ring: 2 groups
#define RH     64               // h2 ring: 4 groups
#define RHP    22               // padded h2 row
#define NCHUNK ((SEQ + CH - 1) / CH)     // 863
#define NBLK   ((NCHUNK + 1) / 2)        // 432 blocks * 2 chunks

typedef unsigned long long u64;
typedef unsigned int u32;

// pack two f32 into f16x2: {lo, hi}
__device__ __forceinline__ u32 pkh2(float lo, float hi) {
    u32 r; asm("cvt.rn.f16x2.f32 %0,%1,%2;" : "=r"(r) : "f"(hi), "f"(lo)); return r;
}
__device__ __forceinline__ void uph2(u32 v, float& lo, float& hi) {
    asm("{.reg .f16 l,h; mov.b32 {l,h},%2; cvt.f32.f16 %0,l; cvt.f32.f16 %1,h;}"
        : "=f"(lo), "=f"(hi) : "r"(v));
}
__device__ __forceinline__ u32 h2fma(u32 a, u32 b, u32 c) {
    u32 d; asm("fma.rn.f16x2 %0,%1,%2,%3;" : "=r"(d) : "r"(a), "r"(b), "r"(c)); return d;
}
__device__ __forceinline__ float tanha(float v) {
    float r; asm("tanh.approx.f32 %0,%1;" : "=f"(r) : "f"(v)); return r;
}
__device__ __forceinline__ float sigf(float v) {
    return fmaf(0.5f, tanha(0.5f * v), 0.5f);
}

__global__ void __launch_bounds__(128, 3) lstm_kernel(
    const float* __restrict__ x,
    const float* __restrict__ w_ih1, const float* __restrict__ w_hh1, const float* __restrict__ b1,
    const float* __restrict__ w_ih2, const float* __restrict__ w_hh2, const float* __restrict__ b2,
    const float* __restrict__ w_p,  const float* __restrict__ b_p,
    float* __restrict__ out)
{
    __shared__ __align__(16) u32   ring1h[2][R1][HID / 2];     // h1 packed f16x2 per step
    __shared__ __align__(16) float ringh[2][RH][RHP];          // h2 fp32 (outproj)
    __shared__ __align__(16) float xbuf[2][2][GROUP * INP];    // staged x per group
    __shared__ int fA[2], fB[2];

    const int tid  = threadIdx.x;
    const int warp = tid >> 5;
    const int lane = tid & 31;
    const int pidx = warp >> 1;        // chunk-pair within block
    const int wflip = (int)(blockIdx.x / 148) & 1;   // SMSP load balance
    const int role = (warp & 1) ^ wflip;             // 0 = A (layer1+io), 1 = B (layer2)
    const int chunk = blockIdx.x * 2 + pidx;
    const int k    = (lane < HID) ? lane : (HID - 1);
    const bool active = (lane < HID);

    if (tid == 0) { fA[0] = -1; fA[1] = -1; fB[0] = -1; fB[1] = -1; }
    __syncthreads();

    int out_begin = 0, out_end = 0, start = 0, ngroups = 0;
    if (chunk < NCHUNK) {
        out_begin = chunk * CH;
        out_end   = (out_begin + CH < SEQ) ? (out_begin + CH) : SEQ;
        start     = (chunk == 0) ? 0 : (out_begin - WARM);
        ngroups   = (out_end - start) >> 4;       // steps multiple of GROUP
    }

    volatile int* vfA = &fA[pidx];
    volatile int* vfB = &fB[pidx];

    if (role == 0) {
        // ========= warp A: xproj + layer-1 recurrence (f16x2) + outproj =========
        u32   wi1h[4][5];            // x-weights as f16x2 pairs (j8 padded with 0)
        u32   whh1h[4][HID / 2];
        float bb1[4];
        #pragma unroll
        for (int g = 0; g < 4; g++) {
            const int row = g * HID + k;
            #pragma unroll
            for (int q = 0; q < 4; q++)
                wi1h[g][q] = pkh2(w_ih1[row * INP + 2 * q], w_ih1[row * INP + 2 * q + 1]);
            wi1h[g][4] = pkh2(w_ih1[row * INP + 8], 0.f);
            bb1[g] = b1[row];
            #pragma unroll
            for (int j = 0; j < HID / 2; j++)
                whh1h[g][j] = pkh2(w_hh1[row * HID + 2 * j], w_hh1[row * HID + 2 * j + 1]);
        }
        const float bp = b_p[0];
        float h = 0.f, c = 0.f;
        u32 hhpair = 0;              // (h_lane, h_lane+1) as f16x2

        auto stagex = [&](int xg) {
            const float4* src = (const float4*)(x + (start + (xg << 4)) * INP);
            float4* dst = (float4*)&xbuf[pidx][xg & 1][0];
            dst[lane] = src[lane];
            if (lane < 4) dst[32 + lane] = src[32 + lane];
        };

        // scalar outproj: once per group, weights via (cached) global loads
        auto outgroup = [&](int og) {
            if (lane < GROUP) {
                const int t = start + (og << 4) + lane;
                if (t >= out_begin && t < out_end) {
                    const int sl = ((og << 4) + lane) & (RH - 1);
                    const float* hp = &ringh[pidx][sl][0];
                    float p = bp;
                    #pragma unroll
                    for (int j = 0; j < HID; j++) p = fmaf(hp[j], __ldg(&w_p[j]), p);
                    out[t] = p;
                }
            }
        };

        if (ngroups > 0) stagex(0);
        __syncwarp();

        for (int g = 0; g < ngroups; g++) {
            if (g + 1 < ngroups) stagex(g + 1);
            while (*vfB < g - 2) { }                // ring1 slots free
            __threadfence_block();

            const float* xb = &xbuf[pidx][g & 1][0];
            #pragma unroll 2
            for (int i = 0; i < GROUP; i++) {
                const int s = (g << 4) + i;
                float xv[INP];
                #pragma unroll
                for (int j = 0; j < INP; j++) xv[j] = xb[i * INP + j];

                u32 px[5];
                #pragma unroll
                for (int q = 0; q < 4; q++) px[q] = pkh2(xv[2 * q], xv[2 * q + 1]);
                px[4] = pkh2(xv[8], 0.f);

                u32 acc[4] = {0u, 0u, 0u, 0u};
                #pragma unroll
                for (int q = 0; q < 5; q++) {
                    #pragma unroll
                    for (int gt = 0; gt < 4; gt++) acc[gt] = h2fma(px[q], wi1h[gt][q], acc[gt]);
                }
                #pragma unroll
                for (int j = 0; j < HID / 2; j++) {
                    const u32 hp = __shfl_sync(0xffffffffu, hhpair, 2 * j);
                    #pragma unroll
                    for (int gt = 0; gt < 4; gt++) acc[gt] = h2fma(hp, whh1h[gt][j], acc[gt]);
                }
                float pa[4];
                #pragma unroll
                for (int gt = 0; gt < 4; gt++) {
                    float lo, hi; uph2(acc[gt], lo, hi);
                    pa[gt] = bb1[gt] + (lo + hi);
                }

                const float ig = sigf(pa[0]);
                const float fg = sigf(pa[1]);
                const float gg = tanha(pa[2]);
                const float og = sigf(pa[3]);
                c = fg * c + ig * gg;
                h = og * tanha(c);

                const float hn = __shfl_down_sync(0xffffffffu, h, 1);
                hhpair = pkh2(h, hn);
                if (active && !(lane & 1))
                    ring1h[pidx][s & (R1 - 1)][lane >> 1] = hhpair;
            }
            __threadfence_block();
            if (lane == 0) *vfA = g;

            if (g >= 1) {
                while (*vfB < g - 1) { }
                __threadfence_block();
                outgroup(g - 1);
            }
            __syncwarp();
        }
        if (ngroups > 0) {
            while (*vfB < ngroups - 1) { }
            __threadfence_block();
            outgroup(ngroups - 1);
        }
    } else {
        // ========= warp B: full layer-2 (f16x2) =========
        u32   wi2h[4][HID / 2], whh2h[4][HID / 2];
        float bb2[4];
        #pragma unroll
        for (int g = 0; g < 4; g++) {
            const int row = g * HID + k;
            #pragma unroll
            for (int j = 0; j < HID / 2; j++) {
                wi2h[g][j]  = pkh2(w_ih2[row * HID + 2 * j], w_ih2[row * HID + 2 * j + 1]);
                whh2h[g][j] = pkh2(w_hh2[row * HID + 2 * j], w_hh2[row * HID + 2 * j + 1]);
            }
            bb2[g] = b2[row];
        }
        float h = 0.f, c = 0.f;
        u32 hh2pair = 0;

        for (int g = 0; g < ngroups; g++) {
            while (*vfA < g) { }
            __threadfence_block();

            #pragma unroll 2
            for (int i = 0; i < GROUP; i++) {
                const int s = (g << 4) + i;
                const u32* h1p = &ring1h[pidx][s & (R1 - 1)][0];

                u32 acc1[4] = {0u, 0u, 0u, 0u};
                u32 acc2[4] = {0u, 0u, 0u, 0u};
                #pragma unroll
                for (int j = 0; j < HID / 2; j++) {
                    const u32 hp1 = h1p[j];
                    const u32 hp2 = __shfl_sync(0xffffffffu, hh2pair, 2 * j);
                    #pragma unroll
                    for (int gt = 0; gt < 4; gt++) {
                        acc1[gt] = h2fma(hp1, wi2h[gt][j], acc1[gt]);
                        acc2[gt] = h2fma(hp2, whh2h[gt][j], acc2[gt]);
                    }
                }
                float pa[4];
                #pragma unroll
                for (int gt = 0; gt < 4; gt++) {
                    float lo1, hi1, lo2, hi2;
                    uph2(acc1[gt], lo1, hi1);
                    uph2(acc2[gt], lo2, hi2);
                    pa[gt] = bb2[gt] + (lo1 + hi1) + (lo2 + hi2);
                }

                const float ig = sigf(pa[0]);
                const float fg = sigf(pa[1]);
                const float gg = tanha(pa[2]);
                const float og = sigf(pa[3]);
                c = fg * c + ig * gg;
                h = og * tanha(c);

                const float hn = __shfl_down_sync(0xffffffffu, h, 1);
                hh2pair = pkh2(h, hn);
                if (active) ringh[pidx][s & (RH - 1)][k] = h;
            }
            __threadfence_block();
            if (lane == 0) *vfB = g;
        }
    }
}

extern "C" void kernel_launch(void* const* d_in, const int* in_sizes, int n_in,
                              void* d_out, int out_size)
{
    const float* x     = (const float*)d_in[0];
    const float* w_ih1 = (const float*)d_in[1];
    const float* w_hh1 = (const float*)d_in[2];
    const float* b1    = (const float*)d_in[3];
    const float* w_ih2 = (const float*)d_in[4];
    const float* w_hh2 = (const float*)d_in[5];
    const float* b2    = (const float*)d_in[6];
    const float* w_p   = (const float*)d_in[7];
    const float* b_p   = (const float*)d_in[8];
    float* out = (float*)d_out;

    lstm_kernel<<<NBLK, 128>>>(x, w_ih1, w_hh1, b1, w_ih2, w_hh2, b2, w_p, b_p, out);
}

// round 16
// speedup vs baseline: 1.1808x; 1.1808x over previous
#include <cuda_runtime.h>

#define SEQ    262144
#define HID    20
#define INP    9
#define CH     224
#define WARM   32
#define GROUP  16
#define HB     32               // h2 staging depth (2 groups)
#define HBP    22               // padded row
#define NCHUNK ((SEQ + CH - 1) / CH)     // 1171
#define NBLK   ((NCHUNK + 3) / 4)        // 293 blocks * 4 chunks

typedef unsigned long long u64;
typedef unsigned int u32;

__device__ __forceinline__ u64 pk2(float lo, float hi) {
    u64 r; asm("mov.b64 %0,{%1,%2};" : "=l"(r) : "f"(lo), "f"(hi)); return r;
}
__device__ __forceinline__ void up2(u64 v, float& lo, float& hi) {
    asm("mov.b64 {%0,%1},%2;" : "=f"(lo), "=f"(hi) : "l"(v));
}
__device__ __forceinline__ u64 fma2(u64 a, u64 b, u64 c) {
    u64 d; asm("fma.rn.f32x2 %0,%1,%2,%3;" : "=l"(d) : "l"(a), "l"(b), "l"(c)); return d;
}
__device__ __forceinline__ u32 pkh2(float lo, float hi) {
    u32 r; asm("cvt.rn.f16x2.f32 %0,%1,%2;" : "=r"(r) : "f"(hi), "f"(lo)); return r;
}
__device__ __forceinline__ void uph2(u32 v, float& lo, float& hi) {
    asm("{.reg .f16 l,h; mov.b32 {l,h},%2; cvt.f32.f16 %0,l; cvt.f32.f16 %1,h;}"
        : "=f"(lo), "=f"(hi) : "r"(v));
}
__device__ __forceinline__ u32 h2fma(u32 a, u32 b, u32 c) {
    u32 d; asm("fma.rn.f16x2 %0,%1,%2,%3;" : "=r"(d) : "r"(a), "r"(b), "r"(c)); return d;
}
__device__ __forceinline__ float tanha(float v) {
    float r; asm("tanh.approx.f32 %0,%1;" : "=f"(r) : "f"(v)); return r;
}
__device__ __forceinline__ float sigf(float v) {
    return fmaf(0.5f, tanha(0.5f * v), 0.5f);
}

__global__ void __launch_bounds__(128, 2) lstm_kernel(
    const float* __restrict__ x,
    const float* __restrict__ w_ih1, const float* __restrict__ w_hh1, const float* __restrict__ b1,
    const float* __restrict__ w_ih2, const float* __restrict__ w_hh2, const float* __restrict__ b2,
    const float* __restrict__ w_p,  const float* __restrict__ b_p,
    float* __restrict__ out)
{
    __shared__ __align__(16) float xbuf[4][2][GROUP * INP];   // staged x per warp
    __shared__ __align__(16) float hgrp[4][HB][HBP];          // h2 staging per warp

    const int warp = threadIdx.x >> 5;
    const int lane = threadIdx.x & 31;
    const int chunk = blockIdx.x * 4 + warp;
    const int k    = (lane < HID) ? lane : (HID - 1);
    const bool active = (lane < HID);
    if (chunk >= NCHUNK) return;

    const int out_begin = chunk * CH;
    const int out_end   = (out_begin + CH < SEQ) ? (out_begin + CH) : SEQ;
    const int start     = (chunk == 0) ? 0 : (out_begin - WARM);
    const int nsteps    = out_end - start;          // multiple of GROUP
    const int ngroups   = nsteps >> 4;

    // ---- weights (per-lane row k) ----
    u32   wi1h[4][5];            // layer1 x-weights f16x2 (j8 padded)
    u32   whh1h[4][HID / 2];     // layer1 hh
    u32   wi2h[4][HID / 2];      // layer2 input (from h1)
    u32   whh2h[4][HID / 2];     // layer2 hh
    float bb1[4], bb2[4];
    u64   wpp[HID / 2];
    #pragma unroll
    for (int g = 0; g < 4; g++) {
        const int r1 = g * HID + k;
        #pragma unroll
        for (int q = 0; q < 4; q++)
            wi1h[g][q] = pkh2(w_ih1[r1 * INP + 2 * q], w_ih1[r1 * INP + 2 * q + 1]);
        wi1h[g][4] = pkh2(w_ih1[r1 * INP + 8], 0.f);
        bb1[g] = b1[r1];
        bb2[g] = b2[r1];
        #pragma unroll
        for (int j = 0; j < HID / 2; j++) {
            whh1h[g][j] = pkh2(w_hh1[r1 * HID + 2 * j], w_hh1[r1 * HID + 2 * j + 1]);
            wi2h[g][j]  = pkh2(w_ih2[r1 * HID + 2 * j], w_ih2[r1 * HID + 2 * j + 1]);
            whh2h[g][j] = pkh2(w_hh2[r1 * HID + 2 * j], w_hh2[r1 * HID + 2 * j + 1]);
        }
    }
    #pragma unroll
    for (int j = 0; j < HID / 2; j++)
        wpp[j] = pk2(w_p[2 * j], w_p[2 * j + 1]);
    const float bp = b_p[0];

    float h1v = 0.f, c1 = 0.f, h2v = 0.f, c2 = 0.f;
    u32 h1pair = 0, h2pair = 0;   // f16x2 (h_lane, h_lane+1) of previous steps

    auto stagex = [&](int xg) {
        const float4* src = (const float4*)(x + (start + (xg << 4)) * INP);
        float4* dst = (float4*)&xbuf[warp][xg & 1][0];
        dst[lane] = src[lane];
        if (lane < 4) dst[32 + lane] = src[32 + lane];
    };

    auto outproj = [&](int g) {
        if (lane < GROUP) {
            const int sg = (g << 4) + lane;
            const int t = start + sg;
            if (t >= out_begin && t < out_end) {
                const u64* hp = (const u64*)&hgrp[warp][sg & (HB - 1)][0];
                u64 a = pk2(0.f, 0.f);
                #pragma unroll
                for (int j = 0; j < HID / 2; j++) a = fma2(hp[j], wpp[j], a);
                float lo, hi; up2(a, lo, hi);
                out[t] = lo + hi + bp;
            }
        }
    };

    stagex(0);
    __syncwarp();

    for (int g = 0; g < ngroups; g++) {
        if (g + 1 < ngroups) stagex(g + 1);
        __syncwarp();          // xbuf[g&1] (staged last group) visible to all lanes

        const float* xb = &xbuf[warp][g & 1][0];
        #pragma unroll 2
        for (int i16 = 0; i16 < GROUP; i16++) {
            const int i = (g << 4) + i16;

            float xv[INP];
            #pragma unroll
            for (int j = 0; j < INP; j++) xv[j] = xb[i16 * INP + j];
            u32 px[5];
            #pragma unroll
            for (int q = 0; q < 4; q++) px[q] = pkh2(xv[2 * q], xv[2 * q + 1]);
            px[4] = pkh2(xv[8], 0.f);

            // layer1 x-projection
            u32 a1[4] = {0u, 0u, 0u, 0u};
            #pragma unroll
            for (int q = 0; q < 5; q++) {
                #pragma unroll
                for (int gt = 0; gt < 4; gt++) a1[gt] = h2fma(px[q], wi1h[gt][q], a1[gt]);
            }

            // shared broadcast of h1[i-1]: feeds layer1 recurrence AND layer2 input
            u32 a2i[4] = {0u, 0u, 0u, 0u};
            u32 a2h[4] = {0u, 0u, 0u, 0u};
            #pragma unroll
            for (int j = 0; j < HID / 2; j++) {
                const u32 b1j = __shfl_sync(0xffffffffu, h1pair, 2 * j);
                const u32 b2j = __shfl_sync(0xffffffffu, h2pair, 2 * j);
                #pragma unroll
                for (int gt = 0; gt < 4; gt++) {
                    a1[gt]  = h2fma(b1j, whh1h[gt][j], a1[gt]);
                    a2i[gt] = h2fma(b1j, wi2h[gt][j],  a2i[gt]);
                    a2h[gt] = h2fma(b2j, whh2h[gt][j], a2h[gt]);
                }
            }

            // layer1 gates -> h1[i]
            float pa1[4];
            #pragma unroll
            for (int gt = 0; gt < 4; gt++) {
                float lo, hi; uph2(a1[gt], lo, hi);
                pa1[gt] = bb1[gt] + (lo + hi);
            }
            {
                const float ig = sigf(pa1[0]);
                const float fg = sigf(pa1[1]);
                const float gg = tanha(pa1[2]);
                const float og = sigf(pa1[3]);
                c1 = fg * c1 + ig * gg;
                h1v = og * tanha(c1);
            }

            // layer2 gates -> h2[i-1]
            float pa2[4];
            #pragma unroll
            for (int gt = 0; gt < 4; gt++) {
                float lo1, hi1, lo2, hi2;
                uph2(a2i[gt], lo1, hi1);
                uph2(a2h[gt], lo2, hi2);
                pa2[gt] = bb2[gt] + (lo1 + hi1) + (lo2 + hi2);
            }
            {
                const float ig = sigf(pa2[0]);
                const float fg = sigf(pa2[1]);
                const float gg = tanha(pa2[2]);
                const float og = sigf(pa2[3]);
                c2 = fg * c2 + ig * gg;
                h2v = og * tanha(c2);
            }

            if (active) hgrp[warp][(i - 1) & (HB - 1)][k] = h2v;  // i=0 writes junk slot 31; overwritten before read

            const float h1n = __shfl_down_sync(0xffffffffu, h1v, 1);
            h1pair = pkh2(h1v, h1n);
            const float h2n = __shfl_down_sync(0xffffffffu, h2v, 1);
            h2pair = pkh2(h2v, h2n);

            if (i == 0) { h2v = 0.f; c2 = 0.f; h2pair = 0u; }  // discard fake h2[-1]
        }

        if (g >= 1) { __syncwarp(); outproj(g - 1); }
    }

    // epilogue: layer2 step nsteps-1
    {
        u32 a2i[4] = {0u, 0u, 0u, 0u};
        u32 a2h[4] = {0u, 0u, 0u, 0u};
        #pragma unroll
        for (int j = 0; j < HID / 2; j++) {
            const u32 b1j = __shfl_sync(0xffffffffu, h1pair, 2 * j);
            const u32 b2j = __shfl_sync(0xffffffffu, h2pair, 2 * j);
            #pragma unroll
            for (int gt = 0; gt < 4; gt++) {
                a2i[gt] = h2fma(b1j, wi2h[gt][j],  a2i[gt]);
                a2h[gt] = h2fma(b2j, whh2h[gt][j], a2h[gt]);
            }
        }
        float pa2[4];
        #pragma unroll
        for (int gt = 0; gt < 4; gt++) {
            float lo1, hi1, lo2, hi2;
            uph2(a2i[gt], lo1, hi1);
            uph2(a2h[gt], lo2, hi2);
            pa2[gt] = bb2[gt] + (lo1 + hi1) + (lo2 + hi2);
        }
        const float ig = sigf(pa2[0]);
        const float fg = sigf(pa2[1]);
        const float gg = tanha(pa2[2]);
        const float og = sigf(pa2[3]);
        c2 = fg * c2 + ig * gg;
        h2v = og * tanha(c2);
        if (active) hgrp[warp][(nsteps - 1) & (HB - 1)][k] = h2v;

        __syncwarp();
        outproj(ngroups - 1);
    }
}

extern "C" void kernel_launch(void* const* d_in, const int* in_sizes, int n_in,
                              void* d_out, int out_size)
{
    const float* x     = (const float*)d_in[0];
    const float* w_ih1 = (const float*)d_in[1];
    const float* w_hh1 = (const float*)d_in[2];
    const float* b1    = (const float*)d_in[3];
    const float* w_ih2 = (const float*)d_in[4];
    const float* w_hh2 = (const float*)d_in[5];
    const float* b2    = (const float*)d_in[6];
    const float* w_p   = (const float*)d_in[7];
    const float* b_p   = (const float*)d_in[8];
    float* out = (float*)d_out;

    lstm_kernel<<<NBLK, 128>>>(x, w_ih1, w_hh1, b1, w_ih2, w_hh2, b2, w_p, b_p, out);
}